// round 15
// baseline (speedup 1.0000x reference)
#include <cuda_runtime.h>
#include <cuda_fp16.h>
#include <cstdint>

// ---------------------------------------------------------------------------
// Problem constants
// ---------------------------------------------------------------------------
#define NB  500000
#define D   300
#define NR  40
#define RD  5
#define NHB 128
#define CH  ((NB + NHB - 1) / NHB)
#define TILE_M    64           // 64-row tiles -> 2 CTAs/SM -> 4 warps/SMSP
#define NTHREADS  256          // 8 warps: 4m x 2n
#define MAX_TILES 256
#define STRIDE_A  616          // halfs: hi 0..303 | sum 304..607 | pad
#define A_BYTES   (TILE_M * STRIDE_A * 2)      // 78848
#define SUB_BYTES  8192        // one 64n x 128B SW128 sub-chunk
#define PAIR_BYTES 16384       // [hi | sum] pair, one bulk op
#define NPAIRS    25           // per r: nc(5) x kc(5)
#define PDEPTH    2
#define ALPHA     256.0f
#define INV_ALPHA 0.00390625f
#define SWZ(o) ((o) ^ (((o) >> 3) & 0x70))

// ---------------------------------------------------------------------------
// Device scratch
// ---------------------------------------------------------------------------
__device__ unsigned char g_Bpk[(size_t)NR * NPAIRS * PAIR_BYTES];  // 16.4 MB
__device__ int g_order[NB];
__device__ int g_offsets[NR + 1];
__device__ int g_blkhist[NHB * NR];
__device__ int g_blkbase[NHB * NR];
__device__ int g_done = 0;

// ---------------------------------------------------------------------------
// Primitives
// ---------------------------------------------------------------------------
__device__ __forceinline__ uint32_t smem_u32(const void* p) {
    uint32_t a;
    asm("{ .reg .u64 t; cvta.to.shared.u64 t, %1; cvt.u32.u64 %0, t; }"
        : "=r"(a) : "l"(p));
    return a;
}
__device__ __forceinline__ void ldsm_x4(uint32_t r[4], uint32_t addr) {
    asm volatile("ldmatrix.sync.aligned.m8n8.x4.shared.b16 {%0,%1,%2,%3}, [%4];"
                 : "=r"(r[0]), "=r"(r[1]), "=r"(r[2]), "=r"(r[3]) : "r"(addr));
}
__device__ __forceinline__ void mma16816(float c[4], const uint32_t a[4],
                                         const uint32_t b0, const uint32_t b1) {
    asm volatile(
        "mma.sync.aligned.m16n8k16.row.col.f32.f16.f16.f32 "
        "{%0,%1,%2,%3}, {%4,%5,%6,%7}, {%8,%9}, {%0,%1,%2,%3};"
        : "+f"(c[0]), "+f"(c[1]), "+f"(c[2]), "+f"(c[3])
        : "r"(a[0]), "r"(a[1]), "r"(a[2]), "r"(a[3]), "r"(b0), "r"(b1));
}
__device__ __forceinline__ void mma16816h(uint32_t c[2], const uint32_t a[4],
                                          const uint32_t b0, const uint32_t b1) {
    asm volatile(
        "mma.sync.aligned.m16n8k16.row.col.f16.f16.f16.f16 "
        "{%0,%1}, {%2,%3,%4,%5}, {%6,%7}, {%0,%1};"
        : "+r"(c[0]), "+r"(c[1])
        : "r"(a[0]), "r"(a[1]), "r"(a[2]), "r"(a[3]), "r"(b0), "r"(b1));
}
__device__ __forceinline__ void bulk_g2s(uint32_t dst, const void* src,
                                         uint32_t bytes, uint32_t mbar) {
    asm volatile(
        "cp.async.bulk.shared::cluster.global.mbarrier::complete_tx::bytes "
        "[%0], [%1], %2, [%3];"
        :: "r"(dst), "l"(src), "r"(bytes), "r"(mbar) : "memory");
}
#define MBARRIER_INIT(mb, cnt) \
    asm volatile("mbarrier.init.shared.b64 [%0], %1;" \
                 :: "r"((uint32_t)(mb)), "r"((uint32_t)(cnt)) : "memory")
#define MBARRIER_EXPECT_TX(mb, n) \
    asm volatile("mbarrier.arrive.expect_tx.shared.b64 _, [%0], %1;" \
                 :: "r"((uint32_t)(mb)), "r"((uint32_t)(n)) : "memory")
#define MBARRIER_ARRIVE(mb) \
    asm volatile("mbarrier.arrive.shared.b64 _, [%0];" \
                 :: "r"((uint32_t)(mb)) : "memory")
#define MBARRIER_WAIT_PARITY(mb, ph) do {                                          \
    uint32_t _m = (uint32_t)(mb); uint32_t _p = (uint32_t)(ph); uint32_t _d;       \
    asm volatile("{\n\t.reg .pred p;\n\t"                                          \
        "mbarrier.try_wait.parity.acquire.cta.shared::cta.b64 p, [%1], %2;\n\t"    \
        "selp.b32 %0, 1, 0, p;\n\t}" : "=r"(_d) : "r"(_m), "r"(_p) : "memory");    \
    if (!_d) {                                                                     \
        asm volatile("{\n\t.reg .pred P1;\n\t"                                     \
            "WL_%=:\n\t"                                                           \
            "mbarrier.try_wait.parity.acquire.cta.shared::cta.b64 P1, [%0], %1, 0x989680;\n\t" \
            "@P1 bra.uni WD_%=;\n\t"                                               \
            "bra.uni WL_%=;\n\t"                                                   \
            "WD_%=:\n\t}" :: "r"(_m), "r"(_p) : "memory");                         \
    }                                                                              \
} while (0)

// ---------------------------------------------------------------------------
// Kernel 1: paired B stream (SW128-swizzled rows in gmem).
// ---------------------------------------------------------------------------
__global__ void k_buildB(const float* __restrict__ rel_table,
                         const float* __restrict__ assoc) {
    __shared__ float sm[64][65];
    int r = blockIdx.x, kc = blockIdx.y / 5, nc = blockIdx.y % 5;
    float rv[RD];
#pragma unroll
    for (int i = 0; i < RD; ++i) rv[i] = rel_table[r * RD + i];
#pragma unroll
    for (int it = 0; it < 16; ++it) {
        int idx = threadIdx.x + it * 256;
        int jl = idx >> 6, nl = idx & 63;
        int j = kc * 64 + jl, n = nc * 64 + nl;
        float v = 0.f;
        if (j < D && n < D) {
#pragma unroll
            for (int i = 0; i < RD; ++i)
                v += rv[i] * assoc[((size_t)i * D + j) * D + n];
        }
        sm[jl][nl] = v;
    }
    __syncthreads();
    size_t pbase = ((size_t)(r * 5 + nc) * 5 + kc) * PAIR_BYTES;
#pragma unroll
    for (int it = 0; it < 16; ++it) {
        int idx = threadIdx.x + it * 256;
        int nl = idx >> 6, jl = idx & 63;
        float v = sm[jl][nl];
        __half hi = __float2half_rn(v);
        float fhi = __half2float(hi);
        __half su = __float2half_rn(fhi + ALPHA * (v - fhi));
        uint32_t off = SWZ((uint32_t)(nl * 128 + jl * 2));
        *(__half*)(g_Bpk + pbase + off) = hi;
        *(__half*)(g_Bpk + pbase + SUB_BYTES + off) = su;
    }
}

// ---------------------------------------------------------------------------
// Kernel 2: fused hist + scan (last-block pattern)
// ---------------------------------------------------------------------------
__global__ void k_histscan(const int* __restrict__ rels) {
    __shared__ int h[NR];
    __shared__ int lastflag;
    if (threadIdx.x < NR) h[threadIdx.x] = 0;
    __syncthreads();
    int start = blockIdx.x * CH, end = min(NB, start + CH);
    for (int i = start + threadIdx.x; i < end; i += blockDim.x)
        atomicAdd(&h[rels[i]], 1);
    __syncthreads();
    if (threadIdx.x < NR) g_blkhist[blockIdx.x * NR + threadIdx.x] = h[threadIdx.x];
    __threadfence();
    if (threadIdx.x == 0)
        lastflag = (atomicAdd(&g_done, 1) == NHB - 1);
    __syncthreads();
    if (lastflag) {
        __threadfence();
        __shared__ int tot[NR];
        int r = threadIdx.x;
        if (r < NR) {
            int run = 0;
            for (int b = 0; b < NHB; b++) {
                g_blkbase[b * NR + r] = run;
                run += g_blkhist[b * NR + r];
            }
            tot[r] = run;
        }
        __syncthreads();
        if (threadIdx.x == 0) {
            int acc = 0;
            for (int rr = 0; rr < NR; rr++) { g_offsets[rr] = acc; acc += tot[rr]; }
            g_offsets[NR] = acc;
            g_done = 0;
        }
        __syncthreads();
        if (r < NR) {
            int off = g_offsets[r];
            for (int b = 0; b < NHB; b++) g_blkbase[b * NR + r] += off;
        }
    }
}

// ---------------------------------------------------------------------------
// Kernel 3: scatter
// ---------------------------------------------------------------------------
__global__ void k_scatter(const int* __restrict__ rels) {
    __shared__ int cur[NR];
    if (threadIdx.x < NR) cur[threadIdx.x] = g_blkbase[blockIdx.x * NR + threadIdx.x];
    __syncthreads();
    int start = blockIdx.x * CH, end = min(NB, start + CH);
    for (int i = start + threadIdx.x; i < end; i += blockDim.x) {
        int pos = atomicAdd(&cur[rels[i]], 1);
        g_order[pos] = i;
    }
}

// ---------------------------------------------------------------------------
// Kernel 4: HMMA energy — INTERLEAVED hi/sum per k16 (8 accumulator chains
// in flight instead of 4; attacks the measured latency bound: occ 24.9%,
// issue 24.0%, tensor 25.6%, L1 47.5%).
// ---------------------------------------------------------------------------
#define SB_OFF    0
#define SA_OFF    (PDEPTH * PAIR_BYTES)                   // 32768
#define MB_OFF    (SA_OFF + A_BYTES)                      // 111616
#define IDX_OFF   (MB_OFF + 64)
#define SEX_OFF   (IDX_OFF + 3 * TILE_M * 4)
#define SMEM_REQ  (SEX_OFF + 2 * TILE_M * 4)              // 112960

extern __shared__ char smem_dyn[];

__global__ __launch_bounds__(NTHREADS, 2)
void k_energy(const int* __restrict__ terms_L,
              const int* __restrict__ terms_R,
              const float* __restrict__ term_table,
              float* __restrict__ out, int r_base) {
    int r = r_base + blockIdx.y;
    int tile = blockIdx.x;
    int lo_off = g_offsets[r];
    int cnt = g_offsets[r + 1] - lo_off;
    if (tile * TILE_M >= cnt) return;
    int base = lo_off + tile * TILE_M;
    int nvalid = min(TILE_M, cnt - tile * TILE_M);

    char* sA = smem_dyn + SA_OFF;
    int* sSid = (int*)(smem_dyn + IDX_OFF);
    int* sIL = sSid + TILE_M;
    int* sIR = sIL + TILE_M;
    float* sEx = (float*)(smem_dyn + SEX_OFF);
    uint32_t u_base = smem_u32(smem_dyn);
    uint32_t u_sB = u_base + SB_OFF;
    uint32_t u_sA = u_base + SA_OFF;
    uint32_t u_mbF = u_base + MB_OFF;
    uint32_t u_mbE = u_base + MB_OFF + 32;

    int tid = threadIdx.x;
    int lane = tid & 31;
    int wid = tid >> 5;
    int wm = wid & 3;       // 4 m-warps x 16 rows
    int wn = wid >> 2;      // 2 n-warps x 32 cols

    if (tid < TILE_M) {
        int sid = (tid < nvalid) ? g_order[base + tid] : -1;
        sSid[tid] = sid;
        sIL[tid] = (sid >= 0) ? terms_L[sid] : 0;
        sIR[tid] = (sid >= 0) ? terms_R[sid] : 0;
    }
    if (tid == 0) {
#pragma unroll
        for (int b = 0; b < PDEPTH; ++b) {
            MBARRIER_INIT(u_mbF + b * 8, 1);
            MBARRIER_INIT(u_mbE + b * 8, 8);
        }
    }
    __syncthreads();

    const unsigned char* bsrc = g_Bpk + (size_t)r * NPAIRS * PAIR_BYTES;
    if (tid == 0) {
#pragma unroll
        for (int p = 0; p < PDEPTH; ++p) {
            MBARRIER_EXPECT_TX(u_mbF + p * 8, PAIR_BYTES);
            bulk_g2s(u_sB + p * PAIR_BYTES, bsrc + (size_t)p * PAIR_BYTES,
                     PAIR_BYTES, u_mbF + p * 8);
        }
    }

    // Build A: fp16 hi (cols 0..303), A' = fp16(hi + ALPHA*res) (cols 304..607)
#pragma unroll 4
    for (int idx = tid; idx < TILE_M * 152; idx += NTHREADS) {
        int m = idx / 152;
        int c2 = (idx % 152) * 2;
        float2 v = make_float2(0.f, 0.f);
        if (c2 < D)
            v = *reinterpret_cast<const float2*>(term_table + (size_t)sIL[m] * D + c2);
        __half hx = __float2half_rn(v.x), hy = __float2half_rn(v.y);
        float fx = __half2float(hx), fy = __half2float(hy);
        __half sx = __float2half_rn(fx + ALPHA * (v.x - fx));
        __half sy = __float2half_rn(fy + ALPHA * (v.y - fy));
        *reinterpret_cast<__half2*>(sA + ((size_t)m * STRIDE_A + c2) * 2) =
            __halves2half2(hx, hy);
        *reinterpret_cast<__half2*>(sA + ((size_t)m * STRIDE_A + 304 + c2) * 2) =
            __halves2half2(sx, sy);
    }
    __syncthreads();

    float c1[4][4];
    uint32_t ch[4][2];
    float e[2] = {0.f, 0.f};

    for (int p = 0; p < NPAIRS; ++p) {
        if (tid == 0 && p >= 1 && (p - 1) + PDEPTH < NPAIRS) {
            int cprev = p - 1;
            int b2 = cprev & 1;
            MBARRIER_WAIT_PARITY(u_mbE + b2 * 8, (cprev >> 1) & 1);
            MBARRIER_EXPECT_TX(u_mbF + b2 * 8, PAIR_BYTES);
            bulk_g2s(u_sB + b2 * PAIR_BYTES,
                     bsrc + (size_t)(cprev + PDEPTH) * PAIR_BYTES,
                     PAIR_BYTES, u_mbF + b2 * 8);
        }

        int b = p & 1;
        MBARRIER_WAIT_PARITY(u_mbF + b * 8, (p >> 1) & 1);

        int nc = p / 5, kc = p - nc * 5;
        if (kc == 0) {
#pragma unroll
            for (int ni = 0; ni < 4; ++ni) {
#pragma unroll
                for (int q = 0; q < 4; ++q) c1[ni][q] = 0.f;
                ch[ni][0] = 0u; ch[ni][1] = 0u;
            }
        }
        uint32_t pairbuf = u_sB + (uint32_t)b * PAIR_BYTES;
        int nilim = (nc == 4 && wn == 1) ? 2 : 4;
        int abase = kc * 64;

        // ---- interleaved hi+sum per k16: 8 accumulator chains in flight ----
#pragma unroll
        for (int k16 = 0; k16 < 4; ++k16) {
            if (kc == 4 && k16 == 3) continue;       // zero pad trim
            int brow = wn * 32 + ((lane >> 4) << 3) + (lane & 7);
            int bcol = k16 * 16 + ((lane >> 3) & 1) * 8;
            uint32_t boff0 = (uint32_t)(brow * 128 + bcol * 2);
            uint32_t boff1 = (uint32_t)((brow + 16) * 128 + bcol * 2);
            int arow = wm * 16 + (lane & 15);
            int acol = abase + k16 * 16 + (lane >> 4) * 8;

            uint32_t bfh[2][4], bfs[2][4];
            ldsm_x4(bfh[0], pairbuf + SWZ(boff0));
            ldsm_x4(bfh[1], pairbuf + SWZ(boff1));
            ldsm_x4(bfs[0], pairbuf + SUB_BYTES + SWZ(boff0));
            ldsm_x4(bfs[1], pairbuf + SUB_BYTES + SWZ(boff1));
            uint32_t ah[4], as[4];
            ldsm_x4(ah, u_sA + (arow * STRIDE_A + acol) * 2);
            ldsm_x4(as, u_sA + (arow * STRIDE_A + 304 + acol) * 2);

            // alternate f32/f16 issues: independent chains hide each other
#pragma unroll
            for (int ni = 0; ni < 4; ++ni) {
                if (ni < nilim) {
                    mma16816(c1[ni], ah, bfh[ni >> 1][(ni & 1) * 2],
                             bfh[ni >> 1][(ni & 1) * 2 + 1]);
                    mma16816h(ch[ni], as, bfs[ni >> 1][(ni & 1) * 2],
                              bfs[ni >> 1][(ni & 1) * 2 + 1]);
                }
            }
        }

        if (lane == 0) MBARRIER_ARRIVE(u_mbE + b * 8);

        if (kc == 4) {
            // epilogue for n-chunk nc: W = c1 + (P - c1)/ALPHA ; e += W . tR
            int row0 = wm * 16 + (lane >> 2);
            int row1 = row0 + 8;
            const float* p0 = term_table + (size_t)sIR[row0] * D;
            const float* p1 = term_table + (size_t)sIR[row1] * D;
#pragma unroll
            for (int ni = 0; ni < 4; ++ni) {
                int col = nc * 64 + wn * 32 + ni * 8 + 2 * (lane & 3);
                if (col < D) {
                    float2 t0 = *reinterpret_cast<const float2*>(p0 + col);
                    float2 t1 = *reinterpret_cast<const float2*>(p1 + col);
                    float2 f0 = __half22float2(
                        *reinterpret_cast<const __half2*>(&ch[ni][0]));
                    float2 f1 = __half22float2(
                        *reinterpret_cast<const __half2*>(&ch[ni][1]));
                    float w00 = c1[ni][0] + (f0.x - c1[ni][0]) * INV_ALPHA;
                    float w01 = c1[ni][1] + (f0.y - c1[ni][1]) * INV_ALPHA;
                    float w10 = c1[ni][2] + (f1.x - c1[ni][2]) * INV_ALPHA;
                    float w11 = c1[ni][3] + (f1.y - c1[ni][3]) * INV_ALPHA;
                    e[0] += w00 * t0.x + w01 * t0.y;
                    e[1] += w10 * t1.x + w11 * t1.y;
                }
            }
        }
    }

    // quad reduce
    float v2[2];
#pragma unroll
    for (int rs = 0; rs < 2; ++rs) {
        float v = e[rs];
        v += __shfl_xor_sync(0xffffffffu, v, 1);
        v += __shfl_xor_sync(0xffffffffu, v, 2);
        v2[rs] = v;
    }

    // 2-way n-warp combine
    __syncthreads();
    if ((lane & 3) == 0) {
#pragma unroll
        for (int rs = 0; rs < 2; ++rs) {
            int m = wm * 16 + (lane >> 2) + rs * 8;
            sEx[wn * TILE_M + m] = v2[rs];
        }
    }
    __syncthreads();
    if (tid < TILE_M) {
        int sid = sSid[tid];
        if (sid >= 0)
            out[sid] = sEx[tid] + sEx[TILE_M + tid];
    }
}

// ---------------------------------------------------------------------------
// launch
// ---------------------------------------------------------------------------
extern "C" void kernel_launch(void* const* d_in, const int* in_sizes, int n_in,
                              void* d_out, int out_size) {
    const int*   rels       = (const int*)d_in[0];
    const int*   terms_L    = (const int*)d_in[1];
    const int*   terms_R    = (const int*)d_in[2];
    const float* term_table = (const float*)d_in[3];
    const float* rel_table  = (const float*)d_in[4];
    const float* assoc      = (const float*)d_in[5];
    float*       out        = (float*)d_out;

    cudaFuncSetAttribute(k_energy, cudaFuncAttributeMaxDynamicSharedMemorySize,
                         SMEM_REQ);

    k_buildB<<<dim3(NR, 25), 256>>>(rel_table, assoc);
    k_histscan<<<NHB, 256>>>(rels);
    k_scatter<<<NHB, 256>>>(rels);
    k_energy<<<dim3(MAX_TILES, 20), NTHREADS, SMEM_REQ>>>(terms_L, terms_R,
                                                          term_table, out, 0);
    k_energy<<<dim3(MAX_TILES, 20), NTHREADS, SMEM_REQ>>>(terms_L, terms_R,
                                                          term_table, out, 20);
}

// round 16
// speedup vs baseline: 1.0349x; 1.0349x over previous
#include <cuda_runtime.h>
#include <cuda_fp16.h>
#include <cstdint>

// ---------------------------------------------------------------------------
// Problem constants
// ---------------------------------------------------------------------------
#define NB  500000
#define D   300
#define NR  40
#define RD  5
#define NHB 128
#define CH  ((NB + NHB - 1) / NHB)
#define TILE_M    64           // 64-row tiles -> 2 CTAs/SM -> 4 warps/SMSP
#define NTHREADS  256          // 8 warps: 4m x 2n
#define MAX_TILES 224          // bucket max ~12.9K << 224*64
#define STRIDE_A  616          // halfs: hi 0..303 | sum 304..607 | pad
#define A_BYTES   (TILE_M * STRIDE_A * 2)      // 78848
#define SUB_BYTES  8192        // one 64n x 128B SW128 sub-chunk
#define PAIR_BYTES 16384       // [hi | sum] pair, one bulk op
#define NPAIRS    25           // per r: nc(5) x kc(5)
#define PDEPTH    2
#define ALPHA     256.0f
#define INV_ALPHA 0.00390625f
#define SWZ(o) ((o) ^ (((o) >> 3) & 0x70))

// ---------------------------------------------------------------------------
// Device scratch
// ---------------------------------------------------------------------------
__device__ unsigned char g_Bpk[(size_t)NR * NPAIRS * PAIR_BYTES];  // 16.4 MB
__device__ int g_order[NB];
__device__ int g_offsets[NR + 1];
__device__ int g_blkhist[NHB * NR];
__device__ int g_blkbase[NHB * NR];
__device__ int g_done = 0;

// ---------------------------------------------------------------------------
// Primitives
// ---------------------------------------------------------------------------
__device__ __forceinline__ uint32_t smem_u32(const void* p) {
    uint32_t a;
    asm("{ .reg .u64 t; cvta.to.shared.u64 t, %1; cvt.u32.u64 %0, t; }"
        : "=r"(a) : "l"(p));
    return a;
}
__device__ __forceinline__ void ldsm_x4(uint32_t r[4], uint32_t addr) {
    asm volatile("ldmatrix.sync.aligned.m8n8.x4.shared.b16 {%0,%1,%2,%3}, [%4];"
                 : "=r"(r[0]), "=r"(r[1]), "=r"(r[2]), "=r"(r[3]) : "r"(addr));
}
__device__ __forceinline__ void mma16816(float c[4], const uint32_t a[4],
                                         const uint32_t b0, const uint32_t b1) {
    asm volatile(
        "mma.sync.aligned.m16n8k16.row.col.f32.f16.f16.f32 "
        "{%0,%1,%2,%3}, {%4,%5,%6,%7}, {%8,%9}, {%0,%1,%2,%3};"
        : "+f"(c[0]), "+f"(c[1]), "+f"(c[2]), "+f"(c[3])
        : "r"(a[0]), "r"(a[1]), "r"(a[2]), "r"(a[3]), "r"(b0), "r"(b1));
}
__device__ __forceinline__ void mma16816h(uint32_t c[2], const uint32_t a[4],
                                          const uint32_t b0, const uint32_t b1) {
    asm volatile(
        "mma.sync.aligned.m16n8k16.row.col.f16.f16.f16.f16 "
        "{%0,%1}, {%2,%3,%4,%5}, {%6,%7}, {%0,%1};"
        : "+r"(c[0]), "+r"(c[1])
        : "r"(a[0]), "r"(a[1]), "r"(a[2]), "r"(a[3]), "r"(b0), "r"(b1));
}
__device__ __forceinline__ void bulk_g2s(uint32_t dst, const void* src,
                                         uint32_t bytes, uint32_t mbar) {
    asm volatile(
        "cp.async.bulk.shared::cluster.global.mbarrier::complete_tx::bytes "
        "[%0], [%1], %2, [%3];"
        :: "r"(dst), "l"(src), "r"(bytes), "r"(mbar) : "memory");
}
#define MBARRIER_INIT(mb, cnt) \
    asm volatile("mbarrier.init.shared.b64 [%0], %1;" \
                 :: "r"((uint32_t)(mb)), "r"((uint32_t)(cnt)) : "memory")
#define MBARRIER_EXPECT_TX(mb, n) \
    asm volatile("mbarrier.arrive.expect_tx.shared.b64 _, [%0], %1;" \
                 :: "r"((uint32_t)(mb)), "r"((uint32_t)(n)) : "memory")
#define MBARRIER_ARRIVE(mb) \
    asm volatile("mbarrier.arrive.shared.b64 _, [%0];" \
                 :: "r"((uint32_t)(mb)) : "memory")
#define MBARRIER_WAIT_PARITY(mb, ph) do {                                          \
    uint32_t _m = (uint32_t)(mb); uint32_t _p = (uint32_t)(ph); uint32_t _d;       \
    asm volatile("{\n\t.reg .pred p;\n\t"                                          \
        "mbarrier.try_wait.parity.acquire.cta.shared::cta.b64 p, [%1], %2;\n\t"    \
        "selp.b32 %0, 1, 0, p;\n\t}" : "=r"(_d) : "r"(_m), "r"(_p) : "memory");    \
    if (!_d) {                                                                     \
        asm volatile("{\n\t.reg .pred P1;\n\t"                                     \
            "WL_%=:\n\t"                                                           \
            "mbarrier.try_wait.parity.acquire.cta.shared::cta.b64 P1, [%0], %1, 0x989680;\n\t" \
            "@P1 bra.uni WD_%=;\n\t"                                               \
            "bra.uni WL_%=;\n\t"                                                   \
            "WD_%=:\n\t}" :: "r"(_m), "r"(_p) : "memory");                         \
    }                                                                              \
} while (0)

// ---------------------------------------------------------------------------
// Kernel 1: paired B stream (SW128-swizzled rows in gmem).
// ---------------------------------------------------------------------------
__global__ void k_buildB(const float* __restrict__ rel_table,
                         const float* __restrict__ assoc) {
    __shared__ float sm[64][65];
    int r = blockIdx.x, kc = blockIdx.y / 5, nc = blockIdx.y % 5;
    float rv[RD];
#pragma unroll
    for (int i = 0; i < RD; ++i) rv[i] = rel_table[r * RD + i];
#pragma unroll
    for (int it = 0; it < 16; ++it) {
        int idx = threadIdx.x + it * 256;
        int jl = idx >> 6, nl = idx & 63;
        int j = kc * 64 + jl, n = nc * 64 + nl;
        float v = 0.f;
        if (j < D && n < D) {
#pragma unroll
            for (int i = 0; i < RD; ++i)
                v += rv[i] * assoc[((size_t)i * D + j) * D + n];
        }
        sm[jl][nl] = v;
    }
    __syncthreads();
    size_t pbase = ((size_t)(r * 5 + nc) * 5 + kc) * PAIR_BYTES;
#pragma unroll
    for (int it = 0; it < 16; ++it) {
        int idx = threadIdx.x + it * 256;
        int nl = idx >> 6, jl = idx & 63;
        float v = sm[jl][nl];
        __half hi = __float2half_rn(v);
        float fhi = __half2float(hi);
        __half su = __float2half_rn(fhi + ALPHA * (v - fhi));
        uint32_t off = SWZ((uint32_t)(nl * 128 + jl * 2));
        *(__half*)(g_Bpk + pbase + off) = hi;
        *(__half*)(g_Bpk + pbase + SUB_BYTES + off) = su;
    }
}

// ---------------------------------------------------------------------------
// Kernel 2: fused hist + scan (last-block pattern)
// ---------------------------------------------------------------------------
__global__ void k_histscan(const int* __restrict__ rels) {
    __shared__ int h[NR];
    __shared__ int lastflag;
    if (threadIdx.x < NR) h[threadIdx.x] = 0;
    __syncthreads();
    int start = blockIdx.x * CH, end = min(NB, start + CH);
    for (int i = start + threadIdx.x; i < end; i += blockDim.x)
        atomicAdd(&h[rels[i]], 1);
    __syncthreads();
    if (threadIdx.x < NR) g_blkhist[blockIdx.x * NR + threadIdx.x] = h[threadIdx.x];
    __threadfence();
    if (threadIdx.x == 0)
        lastflag = (atomicAdd(&g_done, 1) == NHB - 1);
    __syncthreads();
    if (lastflag) {
        __threadfence();
        __shared__ int tot[NR];
        int r = threadIdx.x;
        if (r < NR) {
            int run = 0;
            for (int b = 0; b < NHB; b++) {
                g_blkbase[b * NR + r] = run;
                run += g_blkhist[b * NR + r];
            }
            tot[r] = run;
        }
        __syncthreads();
        if (threadIdx.x == 0) {
            int acc = 0;
            for (int rr = 0; rr < NR; rr++) { g_offsets[rr] = acc; acc += tot[rr]; }
            g_offsets[NR] = acc;
            g_done = 0;
        }
        __syncthreads();
        if (r < NR) {
            int off = g_offsets[r];
            for (int b = 0; b < NHB; b++) g_blkbase[b * NR + r] += off;
        }
    }
}

// ---------------------------------------------------------------------------
// Kernel 3: scatter
// ---------------------------------------------------------------------------
__global__ void k_scatter(const int* __restrict__ rels) {
    __shared__ int cur[NR];
    if (threadIdx.x < NR) cur[threadIdx.x] = g_blkbase[blockIdx.x * NR + threadIdx.x];
    __syncthreads();
    int start = blockIdx.x * CH, end = min(NB, start + CH);
    for (int i = start + threadIdx.x; i < end; i += blockDim.x) {
        int pos = atomicAdd(&cur[rels[i]], 1);
        g_order[pos] = i;
    }
}

// ---------------------------------------------------------------------------
// Kernel 4: HMMA energy — fragment SOFTWARE PIPELINE across k16 (prefetch
// next step's 6 ldsm before issuing this step's 8 MMAs -> ldsm latency
// overlaps MMA issue). Single merged launch (grid y = 40).
// ---------------------------------------------------------------------------
#define SB_OFF    0
#define SA_OFF    (PDEPTH * PAIR_BYTES)                   // 32768
#define MB_OFF    (SA_OFF + A_BYTES)                      // 111616
#define IDX_OFF   (MB_OFF + 64)
#define SEX_OFF   (IDX_OFF + 3 * TILE_M * 4)
#define SMEM_REQ  (SEX_OFF + 2 * TILE_M * 4)              // 112960

extern __shared__ char smem_dyn[];

struct Frags {
    uint32_t bfh[2][4];
    uint32_t bfs[2][4];
    uint32_t ah[4];
    uint32_t as[4];
};

__device__ __forceinline__ void load_frags(Frags& f, uint32_t pairbuf,
                                           uint32_t u_sA, int k16,
                                           int abase, int wn, int wm, int lane) {
    int brow = wn * 32 + ((lane >> 4) << 3) + (lane & 7);
    int bcol = k16 * 16 + ((lane >> 3) & 1) * 8;
    uint32_t boff0 = (uint32_t)(brow * 128 + bcol * 2);
    uint32_t boff1 = (uint32_t)((brow + 16) * 128 + bcol * 2);
    int arow = wm * 16 + (lane & 15);
    int acol = abase + k16 * 16 + (lane >> 4) * 8;
    ldsm_x4(f.bfh[0], pairbuf + SWZ(boff0));
    ldsm_x4(f.bfh[1], pairbuf + SWZ(boff1));
    ldsm_x4(f.bfs[0], pairbuf + SUB_BYTES + SWZ(boff0));
    ldsm_x4(f.bfs[1], pairbuf + SUB_BYTES + SWZ(boff1));
    ldsm_x4(f.ah, u_sA + (arow * STRIDE_A + acol) * 2);
    ldsm_x4(f.as, u_sA + (arow * STRIDE_A + 304 + acol) * 2);
}

__global__ __launch_bounds__(NTHREADS, 2)
void k_energy(const int* __restrict__ terms_L,
              const int* __restrict__ terms_R,
              const float* __restrict__ term_table,
              float* __restrict__ out) {
    int r = blockIdx.y;
    int tile = blockIdx.x;
    int lo_off = g_offsets[r];
    int cnt = g_offsets[r + 1] - lo_off;
    if (tile * TILE_M >= cnt) return;
    int base = lo_off + tile * TILE_M;
    int nvalid = min(TILE_M, cnt - tile * TILE_M);

    char* sA = smem_dyn + SA_OFF;
    int* sSid = (int*)(smem_dyn + IDX_OFF);
    int* sIL = sSid + TILE_M;
    int* sIR = sIL + TILE_M;
    float* sEx = (float*)(smem_dyn + SEX_OFF);
    uint32_t u_base = smem_u32(smem_dyn);
    uint32_t u_sB = u_base + SB_OFF;
    uint32_t u_sA = u_base + SA_OFF;
    uint32_t u_mbF = u_base + MB_OFF;
    uint32_t u_mbE = u_base + MB_OFF + 32;

    int tid = threadIdx.x;
    int lane = tid & 31;
    int wid = tid >> 5;
    int wm = wid & 3;       // 4 m-warps x 16 rows
    int wn = wid >> 2;      // 2 n-warps x 32 cols

    if (tid < TILE_M) {
        int sid = (tid < nvalid) ? g_order[base + tid] : -1;
        sSid[tid] = sid;
        sIL[tid] = (sid >= 0) ? terms_L[sid] : 0;
        sIR[tid] = (sid >= 0) ? terms_R[sid] : 0;
    }
    if (tid == 0) {
#pragma unroll
        for (int b = 0; b < PDEPTH; ++b) {
            MBARRIER_INIT(u_mbF + b * 8, 1);
            MBARRIER_INIT(u_mbE + b * 8, 8);
        }
    }
    __syncthreads();

    const unsigned char* bsrc = g_Bpk + (size_t)r * NPAIRS * PAIR_BYTES;
    if (tid == 0) {
#pragma unroll
        for (int p = 0; p < PDEPTH; ++p) {
            MBARRIER_EXPECT_TX(u_mbF + p * 8, PAIR_BYTES);
            bulk_g2s(u_sB + p * PAIR_BYTES, bsrc + (size_t)p * PAIR_BYTES,
                     PAIR_BYTES, u_mbF + p * 8);
        }
    }

    // Build A: fp16 hi (cols 0..303), A' = fp16(hi + ALPHA*res) (cols 304..607)
#pragma unroll 4
    for (int idx = tid; idx < TILE_M * 152; idx += NTHREADS) {
        int m = idx / 152;
        int c2 = (idx % 152) * 2;
        float2 v = make_float2(0.f, 0.f);
        if (c2 < D)
            v = *reinterpret_cast<const float2*>(term_table + (size_t)sIL[m] * D + c2);
        __half hx = __float2half_rn(v.x), hy = __float2half_rn(v.y);
        float fx = __half2float(hx), fy = __half2float(hy);
        __half sx = __float2half_rn(fx + ALPHA * (v.x - fx));
        __half sy = __float2half_rn(fy + ALPHA * (v.y - fy));
        *reinterpret_cast<__half2*>(sA + ((size_t)m * STRIDE_A + c2) * 2) =
            __halves2half2(hx, hy);
        *reinterpret_cast<__half2*>(sA + ((size_t)m * STRIDE_A + 304 + c2) * 2) =
            __halves2half2(sx, sy);
    }
    __syncthreads();

    float c1[4][4];
    uint32_t ch[4][2];
    float e[2] = {0.f, 0.f};
    Frags fr[2];

    for (int p = 0; p < NPAIRS; ++p) {
        if (tid == 0 && p >= 1 && (p - 1) + PDEPTH < NPAIRS) {
            int cprev = p - 1;
            int b2 = cprev & 1;
            MBARRIER_WAIT_PARITY(u_mbE + b2 * 8, (cprev >> 1) & 1);
            MBARRIER_EXPECT_TX(u_mbF + b2 * 8, PAIR_BYTES);
            bulk_g2s(u_sB + b2 * PAIR_BYTES,
                     bsrc + (size_t)(cprev + PDEPTH) * PAIR_BYTES,
                     PAIR_BYTES, u_mbF + b2 * 8);
        }

        int b = p & 1;
        MBARRIER_WAIT_PARITY(u_mbF + b * 8, (p >> 1) & 1);

        int nc = p / 5, kc = p - nc * 5;
        if (kc == 0) {
#pragma unroll
            for (int ni = 0; ni < 4; ++ni) {
#pragma unroll
                for (int q = 0; q < 4; ++q) c1[ni][q] = 0.f;
                ch[ni][0] = 0u; ch[ni][1] = 0u;
            }
        }
        uint32_t pairbuf = u_sB + (uint32_t)b * PAIR_BYTES;
        int nilim = (nc == 4 && wn == 1) ? 2 : 4;
        int abase = kc * 64;
        int kmax = (kc == 4) ? 3 : 4;        // zero-pad trim

        // fragment software pipeline: prefetch k16+1 before MMAs of k16
        load_frags(fr[0], pairbuf, u_sA, 0, abase, wn, wm, lane);
#pragma unroll
        for (int k16 = 0; k16 < 4; ++k16) {
            if (k16 >= kmax) break;
            int cb = k16 & 1;
            if (k16 + 1 < kmax)
                load_frags(fr[cb ^ 1], pairbuf, u_sA, k16 + 1, abase, wn, wm, lane);
            Frags& f = fr[cb];
#pragma unroll
            for (int ni = 0; ni < 4; ++ni) {
                if (ni < nilim) {
                    mma16816(c1[ni], f.ah, f.bfh[ni >> 1][(ni & 1) * 2],
                             f.bfh[ni >> 1][(ni & 1) * 2 + 1]);
                    mma16816h(ch[ni], f.as, f.bfs[ni >> 1][(ni & 1) * 2],
                              f.bfs[ni >> 1][(ni & 1) * 2 + 1]);
                }
            }
        }

        if (lane == 0) MBARRIER_ARRIVE(u_mbE + b * 8);

        if (kc == 4) {
            // epilogue for n-chunk nc: W = c1 + (P - c1)/ALPHA ; e += W . tR
            int row0 = wm * 16 + (lane >> 2);
            int row1 = row0 + 8;
            const float* p0 = term_table + (size_t)sIR[row0] * D;
            const float* p1 = term_table + (size_t)sIR[row1] * D;
#pragma unroll
            for (int ni = 0; ni < 4; ++ni) {
                int col = nc * 64 + wn * 32 + ni * 8 + 2 * (lane & 3);
                if (col < D) {
                    float2 t0 = *reinterpret_cast<const float2*>(p0 + col);
                    float2 t1 = *reinterpret_cast<const float2*>(p1 + col);
                    float2 f0 = __half22float2(
                        *reinterpret_cast<const __half2*>(&ch[ni][0]));
                    float2 f1 = __half22float2(
                        *reinterpret_cast<const __half2*>(&ch[ni][1]));
                    float w00 = c1[ni][0] + (f0.x - c1[ni][0]) * INV_ALPHA;
                    float w01 = c1[ni][1] + (f0.y - c1[ni][1]) * INV_ALPHA;
                    float w10 = c1[ni][2] + (f1.x - c1[ni][2]) * INV_ALPHA;
                    float w11 = c1[ni][3] + (f1.y - c1[ni][3]) * INV_ALPHA;
                    e[0] += w00 * t0.x + w01 * t0.y;
                    e[1] += w10 * t1.x + w11 * t1.y;
                }
            }
        }
    }

    // quad reduce
    float v2[2];
#pragma unroll
    for (int rs = 0; rs < 2; ++rs) {
        float v = e[rs];
        v += __shfl_xor_sync(0xffffffffu, v, 1);
        v += __shfl_xor_sync(0xffffffffu, v, 2);
        v2[rs] = v;
    }

    // 2-way n-warp combine
    __syncthreads();
    if ((lane & 3) == 0) {
#pragma unroll
        for (int rs = 0; rs < 2; ++rs) {
            int m = wm * 16 + (lane >> 2) + rs * 8;
            sEx[wn * TILE_M + m] = v2[rs];
        }
    }
    __syncthreads();
    if (tid < TILE_M) {
        int sid = sSid[tid];
        if (sid >= 0)
            out[sid] = sEx[tid] + sEx[TILE_M + tid];
    }
}

// ---------------------------------------------------------------------------
// launch (single merged energy launch; still the 4th launch for ncu)
// ---------------------------------------------------------------------------
extern "C" void kernel_launch(void* const* d_in, const int* in_sizes, int n_in,
                              void* d_out, int out_size) {
    const int*   rels       = (const int*)d_in[0];
    const int*   terms_L    = (const int*)d_in[1];
    const int*   terms_R    = (const int*)d_in[2];
    const float* term_table = (const float*)d_in[3];
    const float* rel_table  = (const float*)d_in[4];
    const float* assoc      = (const float*)d_in[5];
    float*       out        = (float*)d_out;

    cudaFuncSetAttribute(k_energy, cudaFuncAttributeMaxDynamicSharedMemorySize,
                         SMEM_REQ);

    k_buildB<<<dim3(NR, 25), 256>>>(rel_table, assoc);
    k_histscan<<<NHB, 256>>>(rels);
    k_scatter<<<NHB, 256>>>(rels);
    k_energy<<<dim3(MAX_TILES, NR), NTHREADS, SMEM_REQ>>>(terms_L, terms_R,
                                                          term_table, out);
}

// round 17
// speedup vs baseline: 1.2259x; 1.1845x over previous
#include <cuda_runtime.h>
#include <cuda_fp16.h>
#include <cstdint>

// ---------------------------------------------------------------------------
// Problem constants
// ---------------------------------------------------------------------------
#define NB  500000
#define D   300
#define NR  40
#define RD  5
#define NHB 128
#define CH  ((NB + NHB - 1) / NHB)
#define TILE_M    64           // 64-row tiles -> 2 CTAs/SM -> 4 warps/SMSP
#define NTHREADS  256          // 8 warps: 4m x 2n
#define MAX_TILES 224          // bucket max ~12.9K << 224*64
#define STRIDE_A  616          // halfs: hi 0..303 | sum 304..607 | pad
#define A_BYTES   (TILE_M * STRIDE_A * 2)      // 78848
#define SUB_BYTES  8192        // one 64n x 128B SW128 sub-chunk
#define PAIR_BYTES 16384       // [hi | sum] pair, one bulk op
#define NPAIRS    25           // per r: nc(5) x kc(5)
#define PDEPTH    2
#define ALPHA     256.0f
#define INV_ALPHA 0.00390625f
#define SWZ(o) ((o) ^ (((o) >> 3) & 0x70))

// ---------------------------------------------------------------------------
// Device scratch
// ---------------------------------------------------------------------------
__device__ unsigned char g_Bpk[(size_t)NR * NPAIRS * PAIR_BYTES];  // 16.4 MB
__device__ int g_order[NB];
__device__ int g_offsets[NR + 1];
__device__ int g_blkhist[NHB * NR];
__device__ int g_blkbase[NHB * NR];
__device__ int g_done = 0;

// ---------------------------------------------------------------------------
// Primitives
// ---------------------------------------------------------------------------
__device__ __forceinline__ uint32_t smem_u32(const void* p) {
    uint32_t a;
    asm("{ .reg .u64 t; cvta.to.shared.u64 t, %1; cvt.u32.u64 %0, t; }"
        : "=r"(a) : "l"(p));
    return a;
}
__device__ __forceinline__ void ldsm_x4(uint32_t r[4], uint32_t addr) {
    asm volatile("ldmatrix.sync.aligned.m8n8.x4.shared.b16 {%0,%1,%2,%3}, [%4];"
                 : "=r"(r[0]), "=r"(r[1]), "=r"(r[2]), "=r"(r[3]) : "r"(addr));
}
__device__ __forceinline__ void mma16816(float c[4], const uint32_t a[4],
                                         const uint32_t b0, const uint32_t b1) {
    asm volatile(
        "mma.sync.aligned.m16n8k16.row.col.f32.f16.f16.f32 "
        "{%0,%1,%2,%3}, {%4,%5,%6,%7}, {%8,%9}, {%0,%1,%2,%3};"
        : "+f"(c[0]), "+f"(c[1]), "+f"(c[2]), "+f"(c[3])
        : "r"(a[0]), "r"(a[1]), "r"(a[2]), "r"(a[3]), "r"(b0), "r"(b1));
}
__device__ __forceinline__ void mma16816h(uint32_t c[2], const uint32_t a[4],
                                          const uint32_t b0, const uint32_t b1) {
    asm volatile(
        "mma.sync.aligned.m16n8k16.row.col.f16.f16.f16.f16 "
        "{%0,%1}, {%2,%3,%4,%5}, {%6,%7}, {%0,%1};"
        : "+r"(c[0]), "+r"(c[1])
        : "r"(a[0]), "r"(a[1]), "r"(a[2]), "r"(a[3]), "r"(b0), "r"(b1));
}
__device__ __forceinline__ void bulk_g2s(uint32_t dst, const void* src,
                                         uint32_t bytes, uint32_t mbar) {
    asm volatile(
        "cp.async.bulk.shared::cluster.global.mbarrier::complete_tx::bytes "
        "[%0], [%1], %2, [%3];"
        :: "r"(dst), "l"(src), "r"(bytes), "r"(mbar) : "memory");
}
#define MBARRIER_INIT(mb, cnt) \
    asm volatile("mbarrier.init.shared.b64 [%0], %1;" \
                 :: "r"((uint32_t)(mb)), "r"((uint32_t)(cnt)) : "memory")
#define MBARRIER_EXPECT_TX(mb, n) \
    asm volatile("mbarrier.arrive.expect_tx.shared.b64 _, [%0], %1;" \
                 :: "r"((uint32_t)(mb)), "r"((uint32_t)(n)) : "memory")
#define MBARRIER_ARRIVE(mb) \
    asm volatile("mbarrier.arrive.shared.b64 _, [%0];" \
                 :: "r"((uint32_t)(mb)) : "memory")
#define MBARRIER_WAIT_PARITY(mb, ph) do {                                          \
    uint32_t _m = (uint32_t)(mb); uint32_t _p = (uint32_t)(ph); uint32_t _d;       \
    asm volatile("{\n\t.reg .pred p;\n\t"                                          \
        "mbarrier.try_wait.parity.acquire.cta.shared::cta.b64 p, [%1], %2;\n\t"    \
        "selp.b32 %0, 1, 0, p;\n\t}" : "=r"(_d) : "r"(_m), "r"(_p) : "memory");    \
    if (!_d) {                                                                     \
        asm volatile("{\n\t.reg .pred P1;\n\t"                                     \
            "WL_%=:\n\t"                                                           \
            "mbarrier.try_wait.parity.acquire.cta.shared::cta.b64 P1, [%0], %1, 0x989680;\n\t" \
            "@P1 bra.uni WD_%=;\n\t"                                               \
            "bra.uni WL_%=;\n\t"                                                   \
            "WD_%=:\n\t}" :: "r"(_m), "r"(_p) : "memory");                         \
    }                                                                              \
} while (0)

// ---------------------------------------------------------------------------
// Kernel 1: paired B stream (SW128-swizzled rows in gmem).
// ---------------------------------------------------------------------------
__global__ void k_buildB(const float* __restrict__ rel_table,
                         const float* __restrict__ assoc) {
    __shared__ float sm[64][65];
    int r = blockIdx.x, kc = blockIdx.y / 5, nc = blockIdx.y % 5;
    float rv[RD];
#pragma unroll
    for (int i = 0; i < RD; ++i) rv[i] = rel_table[r * RD + i];
#pragma unroll
    for (int it = 0; it < 16; ++it) {
        int idx = threadIdx.x + it * 256;
        int jl = idx >> 6, nl = idx & 63;
        int j = kc * 64 + jl, n = nc * 64 + nl;
        float v = 0.f;
        if (j < D && n < D) {
#pragma unroll
            for (int i = 0; i < RD; ++i)
                v += rv[i] * assoc[((size_t)i * D + j) * D + n];
        }
        sm[jl][nl] = v;
    }
    __syncthreads();
    size_t pbase = ((size_t)(r * 5 + nc) * 5 + kc) * PAIR_BYTES;
#pragma unroll
    for (int it = 0; it < 16; ++it) {
        int idx = threadIdx.x + it * 256;
        int nl = idx >> 6, jl = idx & 63;
        float v = sm[jl][nl];
        __half hi = __float2half_rn(v);
        float fhi = __half2float(hi);
        __half su = __float2half_rn(fhi + ALPHA * (v - fhi));
        uint32_t off = SWZ((uint32_t)(nl * 128 + jl * 2));
        *(__half*)(g_Bpk + pbase + off) = hi;
        *(__half*)(g_Bpk + pbase + SUB_BYTES + off) = su;
    }
}

// ---------------------------------------------------------------------------
// Kernel 2: fused hist + scan (last-block pattern)
// ---------------------------------------------------------------------------
__global__ void k_histscan(const int* __restrict__ rels) {
    __shared__ int h[NR];
    __shared__ int lastflag;
    if (threadIdx.x < NR) h[threadIdx.x] = 0;
    __syncthreads();
    int start = blockIdx.x * CH, end = min(NB, start + CH);
    for (int i = start + threadIdx.x; i < end; i += blockDim.x)
        atomicAdd(&h[rels[i]], 1);
    __syncthreads();
    if (threadIdx.x < NR) g_blkhist[blockIdx.x * NR + threadIdx.x] = h[threadIdx.x];
    __threadfence();
    if (threadIdx.x == 0)
        lastflag = (atomicAdd(&g_done, 1) == NHB - 1);
    __syncthreads();
    if (lastflag) {
        __threadfence();
        __shared__ int tot[NR];
        int r = threadIdx.x;
        if (r < NR) {
            int run = 0;
            for (int b = 0; b < NHB; b++) {
                g_blkbase[b * NR + r] = run;
                run += g_blkhist[b * NR + r];
            }
            tot[r] = run;
        }
        __syncthreads();
        if (threadIdx.x == 0) {
            int acc = 0;
            for (int rr = 0; rr < NR; rr++) { g_offsets[rr] = acc; acc += tot[rr]; }
            g_offsets[NR] = acc;
            g_done = 0;
        }
        __syncthreads();
        if (r < NR) {
            int off = g_offsets[r];
            for (int b = 0; b < NHB; b++) g_blkbase[b * NR + r] += off;
        }
    }
}

// ---------------------------------------------------------------------------
// Kernel 3: scatter
// ---------------------------------------------------------------------------
__global__ void k_scatter(const int* __restrict__ rels) {
    __shared__ int cur[NR];
    if (threadIdx.x < NR) cur[threadIdx.x] = g_blkbase[blockIdx.x * NR + threadIdx.x];
    __syncthreads();
    int start = blockIdx.x * CH, end = min(NB, start + CH);
    for (int i = start + threadIdx.x; i < end; i += blockDim.x) {
        int pos = atomicAdd(&cur[rels[i]], 1);
        g_order[pos] = i;
    }
}

// ---------------------------------------------------------------------------
// Kernel 4: HMMA energy — R16 structure + tR epilogue PREFETCH at kc==3
// (one pair ahead; hides the 5 per-nc gather round-trips).
// ---------------------------------------------------------------------------
#define SB_OFF    0
#define SA_OFF    (PDEPTH * PAIR_BYTES)                   // 32768
#define MB_OFF    (SA_OFF + A_BYTES)                      // 111616
#define IDX_OFF   (MB_OFF + 64)
#define SEX_OFF   (IDX_OFF + 3 * TILE_M * 4)
#define SMEM_REQ  (SEX_OFF + 2 * TILE_M * 4)              // 112960

extern __shared__ char smem_dyn[];

struct Frags {
    uint32_t bfh[2][4];
    uint32_t bfs[2][4];
    uint32_t ah[4];
    uint32_t as[4];
};

__device__ __forceinline__ void load_frags(Frags& f, uint32_t pairbuf,
                                           uint32_t u_sA, int k16,
                                           int abase, int wn, int wm, int lane) {
    int brow = wn * 32 + ((lane >> 4) << 3) + (lane & 7);
    int bcol = k16 * 16 + ((lane >> 3) & 1) * 8;
    uint32_t boff0 = (uint32_t)(brow * 128 + bcol * 2);
    uint32_t boff1 = (uint32_t)((brow + 16) * 128 + bcol * 2);
    int arow = wm * 16 + (lane & 15);
    int acol = abase + k16 * 16 + (lane >> 4) * 8;
    ldsm_x4(f.bfh[0], pairbuf + SWZ(boff0));
    ldsm_x4(f.bfh[1], pairbuf + SWZ(boff1));
    ldsm_x4(f.bfs[0], pairbuf + SUB_BYTES + SWZ(boff0));
    ldsm_x4(f.bfs[1], pairbuf + SUB_BYTES + SWZ(boff1));
    ldsm_x4(f.ah, u_sA + (arow * STRIDE_A + acol) * 2);
    ldsm_x4(f.as, u_sA + (arow * STRIDE_A + 304 + acol) * 2);
}

__global__ __launch_bounds__(NTHREADS, 2)
void k_energy(const int* __restrict__ terms_L,
              const int* __restrict__ terms_R,
              const float* __restrict__ term_table,
              float* __restrict__ out) {
    int r = blockIdx.y;
    int tile = blockIdx.x;
    int lo_off = g_offsets[r];
    int cnt = g_offsets[r + 1] - lo_off;
    if (tile * TILE_M >= cnt) return;
    int base = lo_off + tile * TILE_M;
    int nvalid = min(TILE_M, cnt - tile * TILE_M);

    char* sA = smem_dyn + SA_OFF;
    int* sSid = (int*)(smem_dyn + IDX_OFF);
    int* sIL = sSid + TILE_M;
    int* sIR = sIL + TILE_M;
    float* sEx = (float*)(smem_dyn + SEX_OFF);
    uint32_t u_base = smem_u32(smem_dyn);
    uint32_t u_sB = u_base + SB_OFF;
    uint32_t u_sA = u_base + SA_OFF;
    uint32_t u_mbF = u_base + MB_OFF;
    uint32_t u_mbE = u_base + MB_OFF + 32;

    int tid = threadIdx.x;
    int lane = tid & 31;
    int wid = tid >> 5;
    int wm = wid & 3;       // 4 m-warps x 16 rows
    int wn = wid >> 2;      // 2 n-warps x 32 cols

    if (tid < TILE_M) {
        int sid = (tid < nvalid) ? g_order[base + tid] : -1;
        sSid[tid] = sid;
        sIL[tid] = (sid >= 0) ? terms_L[sid] : 0;
        sIR[tid] = (sid >= 0) ? terms_R[sid] : 0;
    }
    if (tid == 0) {
#pragma unroll
        for (int b = 0; b < PDEPTH; ++b) {
            MBARRIER_INIT(u_mbF + b * 8, 1);
            MBARRIER_INIT(u_mbE + b * 8, 8);
        }
    }
    __syncthreads();

    const unsigned char* bsrc = g_Bpk + (size_t)r * NPAIRS * PAIR_BYTES;
    if (tid == 0) {
#pragma unroll
        for (int p = 0; p < PDEPTH; ++p) {
            MBARRIER_EXPECT_TX(u_mbF + p * 8, PAIR_BYTES);
            bulk_g2s(u_sB + p * PAIR_BYTES, bsrc + (size_t)p * PAIR_BYTES,
                     PAIR_BYTES, u_mbF + p * 8);
        }
    }

    // Build A: fp16 hi (cols 0..303), A' = fp16(hi + ALPHA*res) (cols 304..607)
#pragma unroll 4
    for (int idx = tid; idx < TILE_M * 152; idx += NTHREADS) {
        int m = idx / 152;
        int c2 = (idx % 152) * 2;
        float2 v = make_float2(0.f, 0.f);
        if (c2 < D)
            v = *reinterpret_cast<const float2*>(term_table + (size_t)sIL[m] * D + c2);
        __half hx = __float2half_rn(v.x), hy = __float2half_rn(v.y);
        float fx = __half2float(hx), fy = __half2float(hy);
        __half sx = __float2half_rn(fx + ALPHA * (v.x - fx));
        __half sy = __float2half_rn(fy + ALPHA * (v.y - fy));
        *reinterpret_cast<__half2*>(sA + ((size_t)m * STRIDE_A + c2) * 2) =
            __halves2half2(hx, hy);
        *reinterpret_cast<__half2*>(sA + ((size_t)m * STRIDE_A + 304 + c2) * 2) =
            __halves2half2(sx, sy);
    }
    __syncthreads();

    float c1[4][4];
    uint32_t ch[4][2];
    float e[2] = {0.f, 0.f};
    Frags fr[2];
    float2 tp0[4], tp1[4];    // prefetched tR operands (filled at kc==3)

    for (int p = 0; p < NPAIRS; ++p) {
        if (tid == 0 && p >= 1 && (p - 1) + PDEPTH < NPAIRS) {
            int cprev = p - 1;
            int b2 = cprev & 1;
            MBARRIER_WAIT_PARITY(u_mbE + b2 * 8, (cprev >> 1) & 1);
            MBARRIER_EXPECT_TX(u_mbF + b2 * 8, PAIR_BYTES);
            bulk_g2s(u_sB + b2 * PAIR_BYTES,
                     bsrc + (size_t)(cprev + PDEPTH) * PAIR_BYTES,
                     PAIR_BYTES, u_mbF + b2 * 8);
        }

        int b = p & 1;
        MBARRIER_WAIT_PARITY(u_mbF + b * 8, (p >> 1) & 1);

        int nc = p / 5, kc = p - nc * 5;
        if (kc == 0) {
#pragma unroll
            for (int ni = 0; ni < 4; ++ni) {
#pragma unroll
                for (int q = 0; q < 4; ++q) c1[ni][q] = 0.f;
                ch[ni][0] = 0u; ch[ni][1] = 0u;
            }
        }

        // prefetch tR for this nc one pair early (consumed at kc==4)
        if (kc == 3) {
            int row0 = wm * 16 + (lane >> 2);
            int row1 = row0 + 8;
            const float* p0 = term_table + (size_t)sIR[row0] * D;
            const float* p1 = term_table + (size_t)sIR[row1] * D;
#pragma unroll
            for (int ni = 0; ni < 4; ++ni) {
                int col = nc * 64 + wn * 32 + ni * 8 + 2 * (lane & 3);
                tp0[ni] = make_float2(0.f, 0.f);
                tp1[ni] = make_float2(0.f, 0.f);
                if (col < D) {
                    tp0[ni] = __ldg(reinterpret_cast<const float2*>(p0 + col));
                    tp1[ni] = __ldg(reinterpret_cast<const float2*>(p1 + col));
                }
            }
        }

        uint32_t pairbuf = u_sB + (uint32_t)b * PAIR_BYTES;
        int nilim = (nc == 4 && wn == 1) ? 2 : 4;
        int abase = kc * 64;
        int kmax = (kc == 4) ? 3 : 4;        // zero-pad trim

        // fragment software pipeline: prefetch k16+1 before MMAs of k16
        load_frags(fr[0], pairbuf, u_sA, 0, abase, wn, wm, lane);
#pragma unroll
        for (int k16 = 0; k16 < 4; ++k16) {
            if (k16 >= kmax) break;
            int cb = k16 & 1;
            if (k16 + 1 < kmax)
                load_frags(fr[cb ^ 1], pairbuf, u_sA, k16 + 1, abase, wn, wm, lane);
            Frags& f = fr[cb];
#pragma unroll
            for (int ni = 0; ni < 4; ++ni) {
                if (ni < nilim) {
                    mma16816(c1[ni], f.ah, f.bfh[ni >> 1][(ni & 1) * 2],
                             f.bfh[ni >> 1][(ni & 1) * 2 + 1]);
                    mma16816h(ch[ni], f.as, f.bfs[ni >> 1][(ni & 1) * 2],
                              f.bfs[ni >> 1][(ni & 1) * 2 + 1]);
                }
            }
        }

        if (lane == 0) MBARRIER_ARRIVE(u_mbE + b * 8);

        if (kc == 4) {
            // epilogue for nc: W = c1 + (P - c1)/ALPHA ; e += W . tR (prefetched)
#pragma unroll
            for (int ni = 0; ni < 4; ++ni) {
                float2 f0 = __half22float2(
                    *reinterpret_cast<const __half2*>(&ch[ni][0]));
                float2 f1 = __half22float2(
                    *reinterpret_cast<const __half2*>(&ch[ni][1]));
                float w00 = c1[ni][0] + (f0.x - c1[ni][0]) * INV_ALPHA;
                float w01 = c1[ni][1] + (f0.y - c1[ni][1]) * INV_ALPHA;
                float w10 = c1[ni][2] + (f1.x - c1[ni][2]) * INV_ALPHA;
                float w11 = c1[ni][3] + (f1.y - c1[ni][3]) * INV_ALPHA;
                e[0] += w00 * tp0[ni].x + w01 * tp0[ni].y;
                e[1] += w10 * tp1[ni].x + w11 * tp1[ni].y;
            }
        }
    }

    // quad reduce
    float v2[2];
#pragma unroll
    for (int rs = 0; rs < 2; ++rs) {
        float v = e[rs];
        v += __shfl_xor_sync(0xffffffffu, v, 1);
        v += __shfl_xor_sync(0xffffffffu, v, 2);
        v2[rs] = v;
    }

    // 2-way n-warp combine
    __syncthreads();
    if ((lane & 3) == 0) {
#pragma unroll
        for (int rs = 0; rs < 2; ++rs) {
            int m = wm * 16 + (lane >> 2) + rs * 8;
            sEx[wn * TILE_M + m] = v2[rs];
        }
    }
    __syncthreads();
    if (tid < TILE_M) {
        int sid = sSid[tid];
        if (sid >= 0)
            out[sid] = sEx[tid] + sEx[TILE_M + tid];
    }
}

// ---------------------------------------------------------------------------
// launch
// ---------------------------------------------------------------------------
extern "C" void kernel_launch(void* const* d_in, const int* in_sizes, int n_in,
                              void* d_out, int out_size) {
    const int*   rels       = (const int*)d_in[0];
    const int*   terms_L    = (const int*)d_in[1];
    const int*   terms_R    = (const int*)d_in[2];
    const float* term_table = (const float*)d_in[3];
    const float* rel_table  = (const float*)d_in[4];
    const float* assoc      = (const float*)d_in[5];
    float*       out        = (float*)d_out;

    cudaFuncSetAttribute(k_energy, cudaFuncAttributeMaxDynamicSharedMemorySize,
                         SMEM_REQ);

    k_buildB<<<dim3(NR, 25), 256>>>(rel_table, assoc);
    k_histscan<<<NHB, 256>>>(rels);
    k_scatter<<<NHB, 256>>>(rels);
    k_energy<<<dim3(MAX_TILES, NR), NTHREADS, SMEM_REQ>>>(terms_L, terms_R,
                                                          term_table, out);
}